// round 4
// baseline (speedup 1.0000x reference)
#include <cuda_runtime.h>
#include <cstdint>

// Problem constants (fixed shapes per reference)
#define BB 4
#define CC 64
#define NN (512 * 512)
#define KK 400
#define BKK (BB * KK)

// Scratch (no allocations allowed -> __device__ globals)
__device__ float g_sums[BKK * CC];          // [b*K+k][c] accumulator, 409600 B (L2-resident)
__device__ float g_cnt[BKK];                // per-(b,k) pixel counts
__device__ float g_meansT[BB * CC * KK];    // [b][c][k] transposed means for gather

// ---------------------------------------------------------------------------
// Kernel 1: zero the accumulators (graph replays re-run this each iteration)
// ---------------------------------------------------------------------------
__global__ void zero_kernel() {
    int i = blockIdx.x * blockDim.x + threadIdx.x;
    if (i < BKK * CC) g_sums[i] = 0.0f;
    if (i < BKK)      g_cnt[i]  = 0.0f;
}

// ---------------------------------------------------------------------------
// red.global helpers (fire-and-forget L2 reductions; no return path)
// ---------------------------------------------------------------------------
__device__ __forceinline__ void red_add_v4(float* p, float a, float b, float c, float d) {
    asm volatile("red.global.add.v4.f32 [%0], {%1, %2, %3, %4};"
                 :: "l"(p), "f"(a), "f"(b), "f"(c), "f"(d) : "memory");
}
__device__ __forceinline__ void red_add_f32(float* p, float a) {
    asm volatile("red.global.add.f32 [%0], %1;" :: "l"(p), "f"(a) : "memory");
}

// ---------------------------------------------------------------------------
// Kernel 2: accumulate sums + counts.
// Each thread owns 4 consecutive pixels (int4 idx load). For every channel
// group of 4 we issue 4 coalesced LDG.128 (one per channel plane); the
// register transpose is free (just component naming) and each pixel gets one
// 16B red.global.add.v4 into the L2-resident sums table.
// ---------------------------------------------------------------------------
__global__ void accum_kernel(const float* __restrict__ f, const int* __restrict__ idx) {
    const int b = blockIdx.y;
    const int t = blockIdx.x * blockDim.x + threadIdx.x;   // pixel-quad index
    const int n4 = NN / 4;
    if (t >= n4) return;

    const int4 id = reinterpret_cast<const int4*>(idx + (size_t)b * NN)[t];

    red_add_f32(&g_cnt[b * KK + id.x], 1.0f);
    red_add_f32(&g_cnt[b * KK + id.y], 1.0f);
    red_add_f32(&g_cnt[b * KK + id.z], 1.0f);
    red_add_f32(&g_cnt[b * KK + id.w], 1.0f);

    float* s0 = g_sums + (size_t)(b * KK + id.x) * CC;
    float* s1 = g_sums + (size_t)(b * KK + id.y) * CC;
    float* s2 = g_sums + (size_t)(b * KK + id.z) * CC;
    float* s3 = g_sums + (size_t)(b * KK + id.w) * CC;

    const float* fb = f + (size_t)b * CC * NN;

#pragma unroll 2
    for (int c = 0; c < CC; c += 4) {
        const float4 p0 = reinterpret_cast<const float4*>(fb + (size_t)(c + 0) * NN)[t];
        const float4 p1 = reinterpret_cast<const float4*>(fb + (size_t)(c + 1) * NN)[t];
        const float4 p2 = reinterpret_cast<const float4*>(fb + (size_t)(c + 2) * NN)[t];
        const float4 p3 = reinterpret_cast<const float4*>(fb + (size_t)(c + 3) * NN)[t];
        // pixel j's 4 consecutive channels -> one 16B L2 reduction
        red_add_v4(s0 + c, p0.x, p1.x, p2.x, p3.x);
        red_add_v4(s1 + c, p0.y, p1.y, p2.y, p3.y);
        red_add_v4(s2 + c, p0.z, p1.z, p2.z, p3.z);
        red_add_v4(s3 + c, p0.w, p1.w, p2.w, p3.w);
    }
}

// ---------------------------------------------------------------------------
// Kernel 3: means = sums / max(cnt, 1), written transposed to [b][c][k]
// (k-minor so the gather's smem reads land on randomized banks).
// ---------------------------------------------------------------------------
__global__ void finalize_kernel() {
    int i = blockIdx.x * blockDim.x + threadIdx.x;
    if (i >= BKK * CC) return;
    const int bk = i / CC;
    const int c  = i % CC;
    const float cnt = fmaxf(g_cnt[bk], 1.0f);
    const float m = g_sums[i] / cnt;
    const int b = bk / KK;
    const int k = bk % KK;
    g_meansT[((size_t)b * CC + c) * KK + k] = m;
}

// ---------------------------------------------------------------------------
// Kernel 4: gather. Each CTA serves one batch: stage the 64x400 means table
// (100KB) into smem, then stream pixel-quads: 4 scalar LDS per channel
// (banks randomized by idx since stride is 400 floats -> bank = (16c+idx)%32)
// and one coalesced STG.128 per channel. Writes are the DRAM cost; LDS hides
// underneath.
// ---------------------------------------------------------------------------
__global__ void gather_kernel(const int* __restrict__ idx, float* __restrict__ out) {
    extern __shared__ float sm[];   // CC*KK floats = 102400 B
    const int b = blockIdx.y;

    for (int i = threadIdx.x; i < CC * KK; i += blockDim.x)
        sm[i] = g_meansT[(size_t)b * CC * KK + i];
    __syncthreads();

    const int n4 = NN / 4;
    const int4* idx4 = reinterpret_cast<const int4*>(idx + (size_t)b * NN);
    float* outb = out + (size_t)b * CC * NN;

    for (int t = blockIdx.x * blockDim.x + threadIdx.x; t < n4;
         t += gridDim.x * blockDim.x) {
        const int4 id = idx4[t];
#pragma unroll 4
        for (int c = 0; c < CC; c++) {
            float4 o;
            o.x = sm[c * KK + id.x];
            o.y = sm[c * KK + id.y];
            o.z = sm[c * KK + id.z];
            o.w = sm[c * KK + id.w];
            reinterpret_cast<float4*>(outb + (size_t)c * NN)[t] = o;
        }
    }
}

// ---------------------------------------------------------------------------
// Launch: zero -> accumulate -> finalize -> gather (one stream, capturable;
// no allocs, no syncs, no memcpys).
// ---------------------------------------------------------------------------
extern "C" void kernel_launch(void* const* d_in, const int* in_sizes, int n_in,
                              void* d_out, int out_size) {
    const float* features = (const float*)d_in[0];   // [B, C, N] fp32
    const int*   spixel   = (const int*)d_in[1];     // [B, N] int32
    float*       out      = (float*)d_out;           // [B, C, N] fp32

    (void)in_sizes; (void)n_in; (void)out_size;

    // 100KB dynamic smem for the gather kernel (idempotent; capture-safe)
    cudaFuncSetAttribute(gather_kernel,
                         cudaFuncAttributeMaxDynamicSharedMemorySize,
                         CC * KK * (int)sizeof(float));

    {   // zero accumulators
        int n = BKK * CC;
        zero_kernel<<<(n + 255) / 256, 256>>>();
    }
    {   // scatter-reduce
        dim3 grid((NN / 4 + 255) / 256, BB);
        accum_kernel<<<grid, 256>>>(features, spixel);
    }
    {   // means (+ transpose)
        int n = BKK * CC;
        finalize_kernel<<<(n + 255) / 256, 256>>>();
    }
    {   // gather: 74 CTAs x 4 batches = 296 CTAs (2/SM at 100KB smem)
        dim3 grid(74, BB);
        gather_kernel<<<grid, 256, CC * KK * (int)sizeof(float)>>>(spixel, out);
    }
}

// round 5
// speedup vs baseline: 1.9716x; 1.9716x over previous
#include <cuda_runtime.h>
#include <cstdint>

// Problem constants (fixed shapes per reference)
#define BB 4
#define CC 64
#define NN (512 * 512)
#define KK 400
#define BKK (BB * KK)

// Window-sort accumulate config
#define WIN 8192                 // pixels per CTA window
#define NWIN (NN / WIN)          // 32 windows per batch
#define RCH 4                    // channels per staging round
#define NROUND (CC / RCH)        // 16 rounds
#define FPAD (WIN + 4)           // f_sm row stride (floats): 16B-aligned, bank-skewed
#define NSEG (WIN / 32)          // 256 segments of 32 sorted positions
#define ACC_THREADS 1024         // RCH * NSEG

// Scratch (no allocations allowed -> __device__ globals)
__device__ float g_sums[BKK * CC];          // [b*K+k][c], 409600 B (L2-resident)
__device__ float g_cnt[BKK];                // per-(b,k) pixel counts
__device__ float g_meansT[BB * CC * KK];    // [b][c][k] transposed means for gather

// ---------------------------------------------------------------------------
// fire-and-forget L2 reduction
// ---------------------------------------------------------------------------
__device__ __forceinline__ void red_add_f32(float* p, float a) {
    asm volatile("red.global.add.f32 [%0], %1;" :: "l"(p), "f"(a) : "memory");
}

// ---------------------------------------------------------------------------
// Kernel 1: zero the accumulators (graph replays re-run this)
// ---------------------------------------------------------------------------
__global__ void zero_kernel() {
    int i = blockIdx.x * blockDim.x + threadIdx.x;
    if (i < BKK * CC) g_sums[i] = 0.0f;
    if (i < BKK)      g_cnt[i]  = 0.0f;
}

// ---------------------------------------------------------------------------
// Kernel 2: window-sorted accumulate.
// One CTA = one 8192-pixel window of one batch.
//   a) counting-sort local pixel ids by cell in smem (hist -> scan -> scatter)
//   b) red the histogram into g_cnt (counts come free)
//   c) 16 rounds x 4 channels: stage f[c][window] in smem (coalesced),
//      walk sorted order per (seg, channel) thread, combine equal-cell runs
//      in registers, one scalar red.global per run boundary.
// Red element count drops ~8x vs naive scatter (LTS ALU was the bound).
// ---------------------------------------------------------------------------
__global__ __launch_bounds__(ACC_THREADS, 1)
void accum_kernel(const float* __restrict__ f, const int* __restrict__ idx) {
    extern __shared__ char smraw[];
    float*    f_sm   = (float*)smraw;                         // RCH * FPAD floats
    uint32_t* packed = (uint32_t*)(f_sm + RCH * FPAD);        // WIN entries
    int*      hist   = (int*)(packed + WIN);                  // 512
    int*      w      = hist + 512;                            // 512 (scatter cursors)
    int*      scan_s = w + 512;                               // 512

    const int b   = blockIdx.y;
    const int win = blockIdx.x;
    const int tid = threadIdx.x;

    // --- zero histogram (512 for scan padding) ---
    if (tid < 512) hist[tid] = 0;
    __syncthreads();

    // --- load this thread's 8 pixel indices (2 x int4, coalesced) ---
    const int4* idxw = reinterpret_cast<const int4*>(idx + (size_t)b * NN + (size_t)win * WIN);
    const int4 ia = idxw[tid];
    const int4 ib = idxw[tid + ACC_THREADS];

    atomicAdd(&hist[ia.x], 1); atomicAdd(&hist[ia.y], 1);
    atomicAdd(&hist[ia.z], 1); atomicAdd(&hist[ia.w], 1);
    atomicAdd(&hist[ib.x], 1); atomicAdd(&hist[ib.y], 1);
    atomicAdd(&hist[ib.z], 1); atomicAdd(&hist[ib.w], 1);
    __syncthreads();

    // --- red counts into g_cnt (exact: ints in fp32) ---
    if (tid < KK && hist[tid] > 0)
        red_add_f32(&g_cnt[b * KK + tid], (float)hist[tid]);

    // --- Hillis-Steele inclusive scan over 512, then exclusive into w ---
    if (tid < 512) scan_s[tid] = hist[tid];
    __syncthreads();
    for (int d = 1; d < 512; d <<= 1) {
        int v = 0;
        if (tid < 512) {
            v = scan_s[tid];
            if (tid >= d) v += scan_s[tid - d];
        }
        __syncthreads();
        if (tid < 512) scan_s[tid] = v;
        __syncthreads();
    }
    if (tid < 512) w[tid] = scan_s[tid] - hist[tid];   // exclusive prefix
    __syncthreads();

    // --- scatter: sorted order, stored (i, seg)-interleaved so the combine
    //     loop's packed reads are bank-clean. pack cell(9b)<<13 | localpix(13b)
    {
        int lp0 = 4 * tid;
        int lp1 = 4 * (tid + ACC_THREADS);
        int p;
        p = atomicAdd(&w[ia.x], 1); packed[(p & 31) * NSEG + (p >> 5)] = ((uint32_t)ia.x << 13) | (lp0 + 0);
        p = atomicAdd(&w[ia.y], 1); packed[(p & 31) * NSEG + (p >> 5)] = ((uint32_t)ia.y << 13) | (lp0 + 1);
        p = atomicAdd(&w[ia.z], 1); packed[(p & 31) * NSEG + (p >> 5)] = ((uint32_t)ia.z << 13) | (lp0 + 2);
        p = atomicAdd(&w[ia.w], 1); packed[(p & 31) * NSEG + (p >> 5)] = ((uint32_t)ia.w << 13) | (lp0 + 3);
        p = atomicAdd(&w[ib.x], 1); packed[(p & 31) * NSEG + (p >> 5)] = ((uint32_t)ib.x << 13) | (lp1 + 0);
        p = atomicAdd(&w[ib.y], 1); packed[(p & 31) * NSEG + (p >> 5)] = ((uint32_t)ib.y << 13) | (lp1 + 1);
        p = atomicAdd(&w[ib.z], 1); packed[(p & 31) * NSEG + (p >> 5)] = ((uint32_t)ib.z << 13) | (lp1 + 2);
        p = atomicAdd(&w[ib.w], 1); packed[(p & 31) * NSEG + (p >> 5)] = ((uint32_t)ib.w << 13) | (lp1 + 3);
    }
    __syncthreads();

    // --- channel rounds ---
    const float* fwin = f + (size_t)b * CC * NN + (size_t)win * WIN;
    const int c  = tid & (RCH - 1);        // channel within round
    const int s  = tid >> 2;               // segment 0..255
    float* srow_base = g_sums + (size_t)b * KK * CC;

    for (int r = 0; r < NROUND; r++) {
        const int c0 = r * RCH;

        // stage RCH channel rows (coalesced float4 LDG -> conflict-free STS.128)
#pragma unroll
        for (int j = 0; j < RCH; j++) {
            const float4* src = reinterpret_cast<const float4*>(fwin + (size_t)(c0 + j) * NN);
            float4 v0 = src[tid];
            float4 v1 = src[tid + ACC_THREADS];
            *reinterpret_cast<float4*>(&f_sm[j * FPAD + 4 * tid]) = v0;
            *reinterpret_cast<float4*>(&f_sm[j * FPAD + 4 * (tid + ACC_THREADS)]) = v1;
        }
        __syncthreads();

        // combine 32 sorted positions of segment s for channel c0+c
        const float* frow = &f_sm[c * FPAD];
        uint32_t pk = packed[0 * NSEG + s];
        int   cell = pk >> 13;
        float acc  = frow[pk & 8191];
#pragma unroll 4
        for (int i = 1; i < 32; i++) {
            pk = packed[i * NSEG + s];
            const int   cl = pk >> 13;
            const float v  = frow[pk & 8191];
            if (cl != cell) {
                red_add_f32(srow_base + (size_t)cell * CC + c0 + c, acc);
                cell = cl;
                acc = v;
            } else {
                acc += v;
            }
        }
        red_add_f32(srow_base + (size_t)cell * CC + c0 + c, acc);
        __syncthreads();   // before next round overwrites f_sm
    }
}

// ---------------------------------------------------------------------------
// Kernel 3: means = sums / max(cnt,1), transposed to [b][c][k]
// ---------------------------------------------------------------------------
__global__ void finalize_kernel() {
    int i = blockIdx.x * blockDim.x + threadIdx.x;
    if (i >= BKK * CC) return;
    const int bk = i / CC;
    const int c  = i % CC;
    const float cnt = fmaxf(g_cnt[bk], 1.0f);
    const float m = g_sums[i] / cnt;
    const int b = bk / KK;
    const int k = bk % KK;
    g_meansT[((size_t)b * CC + c) * KK + k] = m;
}

// ---------------------------------------------------------------------------
// Kernel 4: gather (512 threads/CTA for occupancy: 2 CTAs x 16 warps / SM).
// ---------------------------------------------------------------------------
__global__ void gather_kernel(const int* __restrict__ idx, float* __restrict__ out) {
    extern __shared__ float sm[];   // CC*KK floats = 102400 B
    const int b = blockIdx.y;

    for (int i = threadIdx.x; i < CC * KK; i += blockDim.x)
        sm[i] = g_meansT[(size_t)b * CC * KK + i];
    __syncthreads();

    const int n4 = NN / 4;
    const int4* idx4 = reinterpret_cast<const int4*>(idx + (size_t)b * NN);
    float* outb = out + (size_t)b * CC * NN;

    for (int t = blockIdx.x * blockDim.x + threadIdx.x; t < n4;
         t += gridDim.x * blockDim.x) {
        const int4 id = idx4[t];
#pragma unroll 4
        for (int c = 0; c < CC; c++) {
            float4 o;
            o.x = sm[c * KK + id.x];
            o.y = sm[c * KK + id.y];
            o.z = sm[c * KK + id.z];
            o.w = sm[c * KK + id.w];
            reinterpret_cast<float4*>(outb + (size_t)c * NN)[t] = o;
        }
    }
}

// ---------------------------------------------------------------------------
// Launch: zero -> window-sort accumulate -> finalize -> gather
// ---------------------------------------------------------------------------
extern "C" void kernel_launch(void* const* d_in, const int* in_sizes, int n_in,
                              void* d_out, int out_size) {
    const float* features = (const float*)d_in[0];   // [B, C, N] fp32
    const int*   spixel   = (const int*)d_in[1];     // [B, N] int32
    float*       out      = (float*)d_out;           // [B, C, N] fp32

    (void)in_sizes; (void)n_in; (void)out_size;

    const int accum_smem = (RCH * FPAD) * 4 + WIN * 4 + 3 * 512 * 4; // ~170 KB
    cudaFuncSetAttribute(accum_kernel,
                         cudaFuncAttributeMaxDynamicSharedMemorySize, accum_smem);
    cudaFuncSetAttribute(gather_kernel,
                         cudaFuncAttributeMaxDynamicSharedMemorySize,
                         CC * KK * (int)sizeof(float));

    {   // zero accumulators
        int n = BKK * CC;
        zero_kernel<<<(n + 255) / 256, 256>>>();
    }
    {   // window-sorted scatter-reduce: 32 windows x 4 batches = 128 CTAs
        dim3 grid(NWIN, BB);
        accum_kernel<<<grid, ACC_THREADS, accum_smem>>>(features, spixel);
    }
    {   // means (+ transpose)
        int n = BKK * CC;
        finalize_kernel<<<(n + 255) / 256, 256>>>();
    }
    {   // gather: 74 x 4 CTAs, 512 threads, 100KB smem (2 CTAs/SM)
        dim3 grid(74, BB);
        gather_kernel<<<grid, 512, CC * KK * (int)sizeof(float)>>>(spixel, out);
    }
}

// round 6
// speedup vs baseline: 2.0850x; 1.0575x over previous
#include <cuda_runtime.h>
#include <cstdint>

// Problem constants (fixed shapes per reference)
#define BB 4
#define CC 64
#define NN (512 * 512)
#define KK 400
#define BKK (BB * KK)

// Window-sort accumulate config (2 CTAs/SM now: smaller window)
#define WIN 4096                 // pixels per CTA window
#define NWIN (NN / WIN)          // 64 windows per batch
#define RCH 4                    // channels per staging round
#define NROUND (CC / RCH)        // 16 rounds
#define FPAD (WIN + 4)           // f_sm row stride (floats)
#define NSEG (WIN / 32)          // 128 segments of 32 sorted positions
#define ACC_THREADS 512          // RCH * NSEG

// Scratch (no allocations allowed -> __device__ globals)
__device__ float g_sums[BKK * CC];          // [b*K+k][c], 409600 B (L2-resident)
__device__ float g_cnt[BKK];                // per-(b,k) pixel counts
__device__ float g_means4[BB * CC * KK];    // [b][c/4][k][c%4] float4-grouped means

// ---------------------------------------------------------------------------
// fire-and-forget L2 reduction
// ---------------------------------------------------------------------------
__device__ __forceinline__ void red_add_f32(float* p, float a) {
    asm volatile("red.global.add.f32 [%0], %1;" :: "l"(p), "f"(a) : "memory");
}

// ---------------------------------------------------------------------------
// Kernel 1: zero the accumulators (graph replays re-run this)
// ---------------------------------------------------------------------------
__global__ void zero_kernel() {
    int i = blockIdx.x * blockDim.x + threadIdx.x;
    if (i < BKK * CC) g_sums[i] = 0.0f;
    if (i < BKK)      g_cnt[i]  = 0.0f;
}

// ---------------------------------------------------------------------------
// Kernel 2: window-sorted accumulate. One CTA = 4096-pixel window.
//   a) counting-sort local pixel ids by cell in smem (hist -> scan -> scatter)
//   b) red histogram into g_cnt
//   c) 16 rounds x 4 channels: stage f[c][window] in smem (coalesced), walk
//      sorted order per (seg, channel) thread, combine equal-cell runs in
//      registers, one scalar red.global per run boundary.
// 88KB smem + <=64 regs -> 2 CTAs/SM: one CTA's combine hides the other's
// staging LDG latency (R4's accum was 1 CTA/SM with staging fully exposed).
// ---------------------------------------------------------------------------
__global__ __launch_bounds__(ACC_THREADS, 2)
void accum_kernel(const float* __restrict__ f, const int* __restrict__ idx) {
    extern __shared__ char smraw[];
    float*    f_sm   = (float*)smraw;                         // RCH * FPAD floats
    uint32_t* packed = (uint32_t*)(f_sm + RCH * FPAD);        // WIN entries
    int*      hist   = (int*)(packed + WIN);                  // 512
    int*      w      = hist + 512;                            // 512 (scatter cursors)
    int*      scan_s = w + 512;                               // 512

    const int b   = blockIdx.y;
    const int win = blockIdx.x;
    const int tid = threadIdx.x;

    // --- zero histogram ---
    hist[tid] = 0;
    __syncthreads();

    // --- this thread's 8 pixel indices (2 x int4, coalesced) ---
    const int4* idxw = reinterpret_cast<const int4*>(idx + (size_t)b * NN + (size_t)win * WIN);
    const int4 ia = idxw[tid];
    const int4 ib = idxw[tid + ACC_THREADS];

    atomicAdd(&hist[ia.x], 1); atomicAdd(&hist[ia.y], 1);
    atomicAdd(&hist[ia.z], 1); atomicAdd(&hist[ia.w], 1);
    atomicAdd(&hist[ib.x], 1); atomicAdd(&hist[ib.y], 1);
    atomicAdd(&hist[ib.z], 1); atomicAdd(&hist[ib.w], 1);
    __syncthreads();

    // --- red counts into g_cnt (exact: small ints in fp32) ---
    if (tid < KK && hist[tid] > 0)
        red_add_f32(&g_cnt[b * KK + tid], (float)hist[tid]);

    // --- Hillis-Steele inclusive scan over 512, exclusive into w ---
    scan_s[tid] = hist[tid];
    __syncthreads();
    for (int d = 1; d < 512; d <<= 1) {
        int v = scan_s[tid];
        if (tid >= d) v += scan_s[tid - d];
        __syncthreads();
        scan_s[tid] = v;
        __syncthreads();
    }
    w[tid] = scan_s[tid] - hist[tid];
    __syncthreads();

    // --- scatter sorted order, (i, seg)-interleaved: pack cell<<12 | localpix
    {
        int lp0 = 4 * tid;
        int lp1 = 4 * (tid + ACC_THREADS);
        int p;
        p = atomicAdd(&w[ia.x], 1); packed[(p & 31) * NSEG + (p >> 5)] = ((uint32_t)ia.x << 12) | (lp0 + 0);
        p = atomicAdd(&w[ia.y], 1); packed[(p & 31) * NSEG + (p >> 5)] = ((uint32_t)ia.y << 12) | (lp0 + 1);
        p = atomicAdd(&w[ia.z], 1); packed[(p & 31) * NSEG + (p >> 5)] = ((uint32_t)ia.z << 12) | (lp0 + 2);
        p = atomicAdd(&w[ia.w], 1); packed[(p & 31) * NSEG + (p >> 5)] = ((uint32_t)ia.w << 12) | (lp0 + 3);
        p = atomicAdd(&w[ib.x], 1); packed[(p & 31) * NSEG + (p >> 5)] = ((uint32_t)ib.x << 12) | (lp1 + 0);
        p = atomicAdd(&w[ib.y], 1); packed[(p & 31) * NSEG + (p >> 5)] = ((uint32_t)ib.y << 12) | (lp1 + 1);
        p = atomicAdd(&w[ib.z], 1); packed[(p & 31) * NSEG + (p >> 5)] = ((uint32_t)ib.z << 12) | (lp1 + 2);
        p = atomicAdd(&w[ib.w], 1); packed[(p & 31) * NSEG + (p >> 5)] = ((uint32_t)ib.w << 12) | (lp1 + 3);
    }
    __syncthreads();

    // --- channel rounds ---
    const float* fwin = f + (size_t)b * CC * NN + (size_t)win * WIN;
    const int c  = tid & (RCH - 1);        // channel within round
    const int s  = tid >> 2;               // segment 0..127
    float* srow_base = g_sums + (size_t)b * KK * CC;

    for (int r = 0; r < NROUND; r++) {
        const int c0 = r * RCH;

        // stage RCH channel rows (coalesced LDG.128 -> STS.128)
#pragma unroll
        for (int j = 0; j < RCH; j++) {
            const float4* src = reinterpret_cast<const float4*>(fwin + (size_t)(c0 + j) * NN);
            float4 v0 = src[tid];
            float4 v1 = src[tid + ACC_THREADS];
            *reinterpret_cast<float4*>(&f_sm[j * FPAD + 4 * tid]) = v0;
            *reinterpret_cast<float4*>(&f_sm[j * FPAD + 4 * (tid + ACC_THREADS)]) = v1;
        }
        __syncthreads();

        // combine 32 sorted positions of segment s for channel c0+c
        const float* frow = &f_sm[c * FPAD];
        uint32_t pk = packed[0 * NSEG + s];
        int   cell = pk >> 12;
        float acc  = frow[pk & 4095];
#pragma unroll 4
        for (int i = 1; i < 32; i++) {
            pk = packed[i * NSEG + s];
            const int   cl = pk >> 12;
            const float v  = frow[pk & 4095];
            if (cl != cell) {
                red_add_f32(srow_base + (size_t)cell * CC + c0 + c, acc);
                cell = cl;
                acc = v;
            } else {
                acc += v;
            }
        }
        red_add_f32(srow_base + (size_t)cell * CC + c0 + c, acc);
        __syncthreads();   // before next round overwrites f_sm
    }
}

// ---------------------------------------------------------------------------
// Kernel 3: means = sums / max(cnt,1), written float4-channel-grouped:
// g_means4[b][c/4][k][c%4]  (so the gather does one LDS.128 per 4 channels)
// ---------------------------------------------------------------------------
__global__ void finalize_kernel() {
    int i = blockIdx.x * blockDim.x + threadIdx.x;
    if (i >= BKK * CC) return;
    const int bk = i / CC;
    const int c  = i % CC;
    const float cnt = fmaxf(g_cnt[bk], 1.0f);
    const float m = g_sums[i] / cnt;
    const int b = bk / KK;
    const int k = bk % KK;
    g_means4[((((size_t)b * (CC / 4) + (c >> 2)) * KK) + k) * 4 + (c & 3)] = m;
}

// ---------------------------------------------------------------------------
// Kernel 4: gather. Table staged as float4 per (c4,k): one LDS.128 fetches
// channels 4c4..4c4+3 of one cell; 4 pixels' quads register-transpose into
// 4 coalesced STG.128 (one per channel plane). 64 LDS.128 + 64 STG.128 per
// pixel-quad iteration (vs 256 scalar LDS before) -> MIO-bound time drops.
// ---------------------------------------------------------------------------
__global__ void gather_kernel(const int* __restrict__ idx, float* __restrict__ out) {
    extern __shared__ float4 sm4[];   // (CC/4)*KK float4 = 102400 B
    const int b = blockIdx.y;

    const float4* tb = reinterpret_cast<const float4*>(g_means4) + (size_t)b * (CC / 4) * KK;
    for (int i = threadIdx.x; i < (CC / 4) * KK; i += blockDim.x)
        sm4[i] = tb[i];
    __syncthreads();

    const int n4 = NN / 4;
    const int4* idx4 = reinterpret_cast<const int4*>(idx + (size_t)b * NN);
    float* outb = out + (size_t)b * CC * NN;

    for (int t = blockIdx.x * blockDim.x + threadIdx.x; t < n4;
         t += gridDim.x * blockDim.x) {
        const int4 id = idx4[t];
#pragma unroll
        for (int c4 = 0; c4 < CC / 4; c4++) {
            const float4 q0 = sm4[c4 * KK + id.x];
            const float4 q1 = sm4[c4 * KK + id.y];
            const float4 q2 = sm4[c4 * KK + id.z];
            const float4 q3 = sm4[c4 * KK + id.w];
            float4* o0 = reinterpret_cast<float4*>(outb + (size_t)(4 * c4 + 0) * NN);
            float4* o1 = reinterpret_cast<float4*>(outb + (size_t)(4 * c4 + 1) * NN);
            float4* o2 = reinterpret_cast<float4*>(outb + (size_t)(4 * c4 + 2) * NN);
            float4* o3 = reinterpret_cast<float4*>(outb + (size_t)(4 * c4 + 3) * NN);
            o0[t] = make_float4(q0.x, q1.x, q2.x, q3.x);
            o1[t] = make_float4(q0.y, q1.y, q2.y, q3.y);
            o2[t] = make_float4(q0.z, q1.z, q2.z, q3.z);
            o3[t] = make_float4(q0.w, q1.w, q2.w, q3.w);
        }
    }
}

// ---------------------------------------------------------------------------
// Launch: zero -> window-sort accumulate -> finalize -> gather
// ---------------------------------------------------------------------------
extern "C" void kernel_launch(void* const* d_in, const int* in_sizes, int n_in,
                              void* d_out, int out_size) {
    const float* features = (const float*)d_in[0];   // [B, C, N] fp32
    const int*   spixel   = (const int*)d_in[1];     // [B, N] int32
    float*       out      = (float*)d_out;           // [B, C, N] fp32

    (void)in_sizes; (void)n_in; (void)out_size;

    const int accum_smem = (RCH * FPAD) * 4 + WIN * 4 + 3 * 512 * 4;  // 88128 B
    cudaFuncSetAttribute(accum_kernel,
                         cudaFuncAttributeMaxDynamicSharedMemorySize, accum_smem);
    cudaFuncSetAttribute(gather_kernel,
                         cudaFuncAttributeMaxDynamicSharedMemorySize,
                         (CC / 4) * KK * (int)sizeof(float4));

    {   // zero accumulators
        int n = BKK * CC;
        zero_kernel<<<(n + 255) / 256, 256>>>();
    }
    {   // window-sorted scatter-reduce: 64 windows x 4 batches = 256 CTAs
        dim3 grid(NWIN, BB);
        accum_kernel<<<grid, ACC_THREADS, accum_smem>>>(features, spixel);
    }
    {   // means (+ channel-group transpose)
        int n = BKK * CC;
        finalize_kernel<<<(n + 255) / 256, 256>>>();
    }
    {   // gather: 74 x 4 CTAs, 512 threads, 100KB smem (2 CTAs/SM)
        dim3 grid(74, BB);
        gather_kernel<<<grid, 512, (CC / 4) * KK * (int)sizeof(float4)>>>(spixel, out);
    }
}